// round 10
// baseline (speedup 1.0000x reference)
#include <cuda_runtime.h>
#include <mma.h>

using namespace nvcuda;

#define Nn   20000
#define PADR 128
#define Ee   640000
#define ENt  660000      // edges + self loops
#define INFt 2048
#define OMt  512
#define NCt  8192
#define C1t  256
#define C2t  128
#define EPSf 1e-5f

// ---------------- device scratch (static, no allocation) ----------------
__device__ int   g_ei64, g_sm64;
__device__ int   d_ROW[ENt], d_COL[ENt];
__device__ float d_deg[Nn], d_dinv[Nn];
__device__ int   d_ecnt[Nn], d_fillc[Nn], d_indptr[Nn + 1];
__device__ int   d_src[ENt];
__device__ float d_cw[ENt];
__device__ int   d_mcnt[OMt], d_mfill[OMt], d_mptr[OMt + 1];
__device__ int   d_min_[NCt], d_mout[NCt], d_sin[NCt];
__device__ float d_mw[NCt], d_sw[NCt];
__device__ float d_h0[(size_t)(Nn + PADR) * OMt];
__device__ float d_g1[(size_t)(Nn + PADR) * C1t], d_h1[(size_t)(Nn + PADR) * C1t];
__device__ float d_g2[(size_t)(Nn + PADR) * C2t], d_h2[(size_t)(Nn + PADR) * C2t];
__device__ float d_sum0[OMt], d_sq0[OMt], d_sum1[C1t], d_sq1[C1t], d_sum2[C2t], d_sq2[C2t];
__device__ float d_W1f[OMt * C1t], d_c1[C1t];
__device__ float d_W2f[C1t * C2t], d_c2[C2t];
__device__ float d_Wlf[C2t * 2],  d_c3[2];

// ---------------- 1: dtype sniff + zero mask counters ----------------
__global__ void k_detect(const unsigned* ei, const unsigned* sm) {
    __shared__ int f0, f1;
    int t = threadIdx.x;
    if (t == 0) { f0 = 0; f1 = 0; }
    __syncthreads();
    if (t < 128) {
        if (ei[2 * t + 1]) atomicOr(&f0, 1);
        if (sm[2 * t + 1]) atomicOr(&f1, 1);
    }
    for (int i = t; i < OMt; i += 128) { d_mcnt[i] = 0; d_mfill[i] = 0; }
    __syncthreads();
    if (t == 0) { g_ei64 = (f0 == 0); g_sm64 = (f1 == 0); }
}

// ---------------- 2: decode sparse mask + count per out column ----------------
__global__ void k_maskcount(const void* smv, const float* __restrict__ smw) {
    int j = blockIdx.x * blockDim.x + threadIdx.x;
    if (j >= NCt) return;
    int a, b;
    if (g_sm64) {
        const long long* p = (const long long*)smv;
        a = (int)p[2 * j]; b = (int)p[2 * j + 1];
    } else {
        const int* p = (const int*)smv;
        a = p[2 * j]; b = p[2 * j + 1];
    }
    d_min_[j] = a; d_mout[j] = b; d_mw[j] = smw[j];
    atomicAdd(&d_mcnt[b], 1);
}

// ---------------- 3: single block: scan 512 mask counts + CSC fill ----------------
__global__ void __launch_bounds__(512) k_mask_scanfill() {
    __shared__ int wsum[16];
    int t = threadIdx.x;
    int lane = t & 31, warp = t >> 5;
    int v = d_mcnt[t];
    int s = v;
#pragma unroll
    for (int off = 1; off < 32; off <<= 1) {
        int u = __shfl_up_sync(~0u, s, off);
        if (lane >= off) s += u;
    }
    if (lane == 31) wsum[warp] = s;
    __syncthreads();
    if (warp == 0 && lane < 16) {
        int w = wsum[lane];
#pragma unroll
        for (int off = 1; off < 16; off <<= 1) {
            int u = __shfl_up_sync(0xffffu, w, off);
            if (lane >= off) w += u;
        }
        wsum[lane] = w;
    }
    __syncthreads();
    int incl = s + (warp ? wsum[warp - 1] : 0);
    d_mptr[t] = incl - v;
    if (t == 511) d_mptr[OMt] = incl;
    __syncthreads();
    for (int j = t; j < NCt; j += 512) {
        int b = d_mout[j];
        int p = d_mptr[b] + atomicAdd(&d_mfill[b], 1);
        d_sin[p] = d_min_[j];
        d_sw[p] = d_mw[j];
    }
}

// ---------------- 4 (PROFILED): sparse masked linear + ReLU ----------------
#define NPB 4
__global__ void __launch_bounds__(512) k_stageA(const float* __restrict__ x,
                                                const float* __restrict__ smb) {
    __shared__ float4 xs4[INFt];
    int node0 = blockIdx.x * NPB;
    int t = threadIdx.x;
    const float* x0 = x + (size_t)node0 * INFt;
#pragma unroll
    for (int i = 0; i < INFt / 512; i++) {
        int f = t + i * 512;
        float4 v;
        v.x = __ldg(&x0[f]);
        v.y = __ldg(&x0[f + INFt]);
        v.z = __ldg(&x0[f + 2 * INFt]);
        v.w = __ldg(&x0[f + 3 * INFt]);
        xs4[f] = v;
    }
    __syncthreads();
    int o = t;
    float a0 = 0.f, a1 = 0.f, a2 = 0.f, a3 = 0.f;
    int p0 = d_mptr[o], p1 = d_mptr[o + 1];
    for (int p = p0; p < p1; p++) {
        int idx = d_sin[p];
        float w = d_sw[p];
        float4 v = xs4[idx];
        a0 += v.x * w;
        a1 += v.y * w;
        a2 += v.z * w;
        a3 += v.w * w;
    }
    float b = smb[o];
    d_h0[(size_t)(node0 + 0) * OMt + o] = fmaxf(a0 + b, 0.f);
    d_h0[(size_t)(node0 + 1) * OMt + o] = fmaxf(a1 + b, 0.f);
    d_h0[(size_t)(node0 + 2) * OMt + o] = fmaxf(a2 + b, 0.f);
    d_h0[(size_t)(node0 + 3) * OMt + o] = fmaxf(a3 + b, 0.f);
}

// ---------------- 5: zero edge counters + BN accumulators ----------------
__global__ void k_zero() {
    int i = blockIdx.x * blockDim.x + threadIdx.x;
    if (i < Nn)  { d_deg[i] = 0.f; d_ecnt[i] = 0; d_fillc[i] = 0; }
    if (i < OMt) { d_sum0[i] = 0.f; d_sq0[i] = 0.f; }
    if (i < C1t) { d_sum1[i] = 0.f; d_sq1[i] = 0.f; }
    if (i < C2t) { d_sum2[i] = 0.f; d_sq2[i] = 0.f; }
}

// ---------------- 6: decode edges + per-col degree/count ----------------
__global__ void k_edges(const void* eiv, const float* __restrict__ ew) {
    int e = blockIdx.x * blockDim.x + threadIdx.x;
    if (e >= ENt) return;
    int r, c;
    if (e < Ee) {
        if (g_ei64) {
            const long long* p = (const long long*)eiv;
            r = (int)p[e]; c = (int)p[Ee + e];
        } else {
            const int* p = (const int*)eiv;
            r = p[e]; c = p[Ee + e];
        }
    } else { r = c = e - Ee; }
    float w = (e < Ee) ? ew[e] : 1.f;
    d_ROW[e] = r; d_COL[e] = c;
    atomicAdd(&d_deg[c], w);
    atomicAdd(&d_ecnt[c], 1);
}

// ---------------- 7: shuffle-scan indptr (20000) + dinv ----------------
__global__ void __launch_bounds__(1024) k_scan_dinv() {
    __shared__ int wsum[32];
    const int CH = 20;
    int t = threadIdx.x;
    int lane = t & 31, warp = t >> 5;
    int base = t * CH;
    int cnts[CH];
    int loc = 0;
#pragma unroll
    for (int i = 0; i < CH; i++) {
        int v = (base + i < Nn) ? __ldg(&d_ecnt[base + i]) : 0;
        cnts[i] = v; loc += v;
    }
    int s = loc;
#pragma unroll
    for (int off = 1; off < 32; off <<= 1) {
        int u = __shfl_up_sync(~0u, s, off);
        if (lane >= off) s += u;
    }
    if (lane == 31) wsum[warp] = s;
    __syncthreads();
    if (warp == 0) {
        int w = wsum[lane];
#pragma unroll
        for (int off = 1; off < 32; off <<= 1) {
            int u = __shfl_up_sync(~0u, w, off);
            if (lane >= off) w += u;
        }
        wsum[lane] = w;
    }
    __syncthreads();
    int run = s - loc + (warp ? wsum[warp - 1] : 0);
#pragma unroll
    for (int i = 0; i < CH; i++) {
        if (base + i < Nn) d_indptr[base + i] = run;
        run += cnts[i];
    }
    if (t == 1023) d_indptr[Nn] = run;
    for (int i = t; i < Nn; i += 1024) {
        float dg = d_deg[i];
        d_dinv[i] = (dg > 0.f) ? rsqrtf(dg) : 0.f;
    }
}

// ---------------- 8: CSR fill with normalized weights ----------------
__global__ void k_fill(const float* __restrict__ ew) {
    int e = blockIdx.x * blockDim.x + threadIdx.x;
    if (e >= ENt) return;
    int c = d_COL[e], r = d_ROW[e];
    int p = d_indptr[c] + atomicAdd(&d_fillc[c], 1);
    float w = (e < Ee) ? ew[e] : 1.f;
    d_src[p] = r;
    d_cw[p] = d_dinv[r] * w * d_dinv[c];
}

// ---------------- column stats (low-contention: 256 blocks) ----------------
__global__ void k_stats(const float* __restrict__ in, float* __restrict__ sum,
                        float* __restrict__ sq, int F) {
    int t = threadIdx.x;   // blockDim == F
    float s = 0.f, q = 0.f;
    for (int r = blockIdx.x; r < Nn; r += gridDim.x) {
        float v = in[(size_t)r * F + t];
        s += v; q += v * v;
    }
    atomicAdd(&sum[t], s);
    atomicAdd(&sq[t], q);
}

// ---------------- merged BN-fold: Wf = a⊙W (rows), c = d@W (+addb) ----------------
__global__ void __launch_bounds__(256) k_prep(
    const float* __restrict__ W, const float* __restrict__ sum,
    const float* __restrict__ sq, const float* __restrict__ g,
    const float* __restrict__ b, const float* __restrict__ addb,
    float* __restrict__ Wf, float* __restrict__ cvec, int Kd, int Nd) {
    int t = threadIdx.x;
    if (blockIdx.x + 1 < gridDim.x) {
        int i = blockIdx.x * 256 + t;
        if (i < Kd * Nd) {
            int k = i / Nd;
            float m = sum[k] * (1.f / Nn);
            float v = fmaxf(sq[k] * (1.f / Nn) - m * m, 0.f);
            float s = g[k] * rsqrtf(v + EPSf);
            Wf[i] = s * W[i];
        }
    } else {
        __shared__ float dsh[512];
        for (int k = t; k < Kd; k += 256) {
            float m = sum[k] * (1.f / Nn);
            float v = fmaxf(sq[k] * (1.f / Nn) - m * m, 0.f);
            float s = g[k] * rsqrtf(v + EPSf);
            dsh[k] = b[k] - m * s;
        }
        __syncthreads();
        if (t < Nd) {
            float s = addb ? addb[t] : 0.f;
            for (int k = 0; k < Kd; k++) s += dsh[k] * W[k * Nd + t];
            cvec[t] = s;
        }
    }
}

// ---------------- split-tf32 wmma GEMM: C[M,Nd] = A[M,K] @ B[K,Nd] ----------------
// 128x128 block tile, 8 warps (4x2), warp tile 32x64, K-tile 32.
// Accuracy: A=Ahi+Alo, B=Bhi+Blo (tf32 splits); C ~= AhiBhi + AloBhi + AhiBlo.
// A, C padded to Nn+PADR rows -> no row guards.
#define KT  32
#define LDA 40
#define LDB 136
__global__ void __launch_bounds__(256)
k_gemm(const float* __restrict__ A, const float* __restrict__ B,
       float* __restrict__ C, int K, int Nd) {
    __shared__ __align__(16) float As[128][LDA];
    __shared__ __align__(16) float Bs[KT][LDB];
    int t = threadIdx.x;
    int warp = t >> 5;
    int wm = warp & 3, wn = warp >> 2;
    int mb = blockIdx.x * 128, nb = blockIdx.y * 128;

    wmma::fragment<wmma::accumulator, 16, 16, 8, float> acc[2][4];
#pragma unroll
    for (int i = 0; i < 2; i++)
#pragma unroll
        for (int j = 0; j < 4; j++) wmma::fill_fragment(acc[i][j], 0.f);

    for (int kt = 0; kt < K; kt += KT) {
#pragma unroll
        for (int i = 0; i < 4; i++) {
            int li = t + i * 256;             // 1024 float4 = 128 rows x 8 quads
            int row = li >> 3, cq = li & 7;
            float4 v = *(const float4*)(A + (size_t)(mb + row) * K + kt + cq * 4);
            *(float4*)&As[row][cq * 4] = v;
        }
#pragma unroll
        for (int i = 0; i < 4; i++) {
            int li = t + i * 256;             // 1024 float4 = 32 rows x 32 quads
            int row = li >> 5, cq = li & 31;
            float4 v = *(const float4*)(B + (size_t)(kt + row) * Nd + nb + cq * 4);
            *(float4*)&Bs[row][cq * 4] = v;
        }
        __syncthreads();
#pragma unroll
        for (int ks = 0; ks < KT; ks += 8) {
            wmma::fragment<wmma::matrix_a, 16, 16, 8, wmma::precision::tf32,
                           wmma::row_major> ahi[2], alo[2];
#pragma unroll
            for (int i = 0; i < 2; i++) {
                wmma::fragment<wmma::matrix_a, 16, 16, 8, wmma::precision::tf32,
                               wmma::row_major> ar;
                wmma::load_matrix_sync(ar, &As[wm * 32 + i * 16][ks], LDA);
#pragma unroll
                for (int e = 0; e < ar.num_elements; e++) {
                    float v = ar.x[e];
                    float h = wmma::__float_to_tf32(v);
                    ahi[i].x[e] = h;
                    alo[i].x[e] = wmma::__float_to_tf32(v - h);
                }
            }
#pragma unroll
            for (int j = 0; j < 4; j++) {
                wmma::fragment<wmma::matrix_b, 16, 16, 8, wmma::precision::tf32,
                               wmma::row_major> br, bhi, blo;
                wmma::load_matrix_sync(br, &Bs[ks][wn * 64 + j * 16], LDB);
#pragma unroll
                for (int e = 0; e < br.num_elements; e++) {
                    float v = br.x[e];
                    float h = wmma::__float_to_tf32(v);
                    bhi.x[e] = h;
                    blo.x[e] = wmma::__float_to_tf32(v - h);
                }
#pragma unroll
                for (int i = 0; i < 2; i++) {
                    wmma::mma_sync(acc[i][j], ahi[i], bhi, acc[i][j]);
                    wmma::mma_sync(acc[i][j], alo[i], bhi, acc[i][j]);
                    wmma::mma_sync(acc[i][j], ahi[i], blo, acc[i][j]);
                }
            }
        }
        __syncthreads();
    }
#pragma unroll
    for (int i = 0; i < 2; i++)
#pragma unroll
        for (int j = 0; j < 4; j++)
            wmma::store_matrix_sync(
                C + (size_t)(mb + wm * 32 + i * 16) * Nd + nb + wn * 64 + j * 16,
                acc[i][j], Nd, wmma::mem_row_major);
}

// ---------------- CSR agg: out[n] = relu(sum w*g[src] + (sum w)*cv + bias) ----------------
__global__ void k_agg(const float* __restrict__ g, const float* __restrict__ cv,
                      const float* __restrict__ bias, float* __restrict__ out, int F) {
    int n = blockIdx.x, t = threadIdx.x;
    int s0 = d_indptr[n], s1 = d_indptr[n + 1];
    float acc = 0.f, ws = 0.f;
    for (int e = s0; e < s1; e++) {
        int s = __ldg(&d_src[e]);
        float w = __ldg(&d_cw[e]);
        ws += w;
        acc += g[(size_t)s * F + t] * w;
    }
    out[(size_t)n * F + t] = fmaxf(acc + ws * cv[t] + bias[t], 0.f);
}

// ---------------- final linear: out[n,:2] = h2[n,:] @ Wlf + c3 ----------------
__global__ void k_final(float* __restrict__ out) {
    int w = blockIdx.x * 8 + (threadIdx.x >> 5);
    int lane = threadIdx.x & 31;
    if (w >= Nn) return;
    float4 v = ((const float4*)(d_h2 + (size_t)w * C2t))[lane];
    float4 w0 = ((const float4*)d_Wlf)[lane * 2];
    float4 w1 = ((const float4*)d_Wlf)[lane * 2 + 1];
    float s0 = v.x * w0.x + v.y * w0.z + v.z * w1.x + v.w * w1.z;
    float s1 = v.x * w0.y + v.y * w0.w + v.z * w1.y + v.w * w1.w;
#pragma unroll
    for (int off = 16; off; off >>= 1) {
        s0 += __shfl_down_sync(0xffffffffu, s0, off);
        s1 += __shfl_down_sync(0xffffffffu, s1, off);
    }
    if (lane == 0) {
        out[w * 2 + 0] = s0 + d_c3[0];
        out[w * 2 + 1] = s1 + d_c3[1];
    }
}

// ---------------- host launch ----------------
extern "C" void kernel_launch(void* const* d_in, const int* in_sizes, int n_in,
                              void* d_out, int out_size) {
    const float* x     = (const float*)d_in[0];
    const void*  ei    = d_in[1];
    const float* ew    = (const float*)d_in[2];
    const void*  sm    = d_in[3];
    const float* smw   = (const float*)d_in[4];
    const float* smb   = (const float*)d_in[5];
    const float* bnsg  = (const float*)d_in[6];
    const float* bnsb  = (const float*)d_in[7];
    const float* W1    = (const float*)d_in[8];
    const float* b1    = (const float*)d_in[9];
    const float* bn1g  = (const float*)d_in[10];
    const float* bn1b  = (const float*)d_in[11];
    const float* W2    = (const float*)d_in[12];
    const float* b2    = (const float*)d_in[13];
    const float* bn2g  = (const float*)d_in[14];
    const float* bn2b  = (const float*)d_in[15];
    const float* linW  = (const float*)d_in[16];
    const float* linb  = (const float*)d_in[17];
    float* out = (float*)d_out;

    float *p_h0, *p_g1, *p_h1, *p_g2, *p_h2;
    float *p_W1f, *p_W2f, *p_Wlf, *p_c1, *p_c2, *p_c3;
    float *p_s0, *p_q0, *p_s1, *p_q1, *p_s2, *p_q2;
    cudaGetSymbolAddress((void**)&p_h0, d_h0);
    cudaGetSymbolAddress((void**)&p_g1, d_g1);
    cudaGetSymbolAddress((void**)&p_h1, d_h1);
    cudaGetSymbolAddress((void**)&p_g2, d_g2);
    cudaGetSymbolAddress((void**)&p_h2, d_h2);
    cudaGetSymbolAddress((void**)&p_W1f, d_W1f);
    cudaGetSymbolAddress((void**)&p_W2f, d_W2f);
    cudaGetSymbolAddress((void**)&p_Wlf, d_Wlf);
    cudaGetSymbolAddress((void**)&p_c1, d_c1);
    cudaGetSymbolAddress((void**)&p_c2, d_c2);
    cudaGetSymbolAddress((void**)&p_c3, d_c3);
    cudaGetSymbolAddress((void**)&p_s0, d_sum0);
    cudaGetSymbolAddress((void**)&p_q0, d_sq0);
    cudaGetSymbolAddress((void**)&p_s1, d_sum1);
    cudaGetSymbolAddress((void**)&p_q1, d_sq1);
    cudaGetSymbolAddress((void**)&p_s2, d_sum2);
    cudaGetSymbolAddress((void**)&p_q2, d_sq2);

    k_detect<<<1, 128>>>((const unsigned*)ei, (const unsigned*)sm);    // 1
    k_maskcount<<<32, 256>>>(sm, smw);                                 // 2
    k_mask_scanfill<<<1, 512>>>();                                     // 3
    k_stageA<<<Nn / NPB, 512>>>(x, smb);                               // 4 <- ncu capture
    k_zero<<<(Nn + 255) / 256, 256>>>();                               // 5
    k_edges<<<(ENt + 255) / 256, 256>>>(ei, ew);                       // 6
    k_scan_dinv<<<1, 1024>>>();                                        // 7
    k_fill<<<(ENt + 255) / 256, 256>>>(ew);                            // 8

    k_stats<<<256, 512>>>(p_h0, p_s0, p_q0, OMt);                      // 9
    k_prep<<<(OMt * C1t + 255) / 256 + 1, 256>>>(W1, p_s0, p_q0, bnsg, bnsb,
                                                 nullptr, p_W1f, p_c1, OMt, C1t);
    k_gemm<<<dim3((Nn + 127) / 128, C1t / 128), 256>>>(p_h0, p_W1f, p_g1, OMt, C1t);
    k_agg<<<Nn, C1t>>>(p_g1, p_c1, b1, p_h1, C1t);

    k_stats<<<256, 256>>>(p_h1, p_s1, p_q1, C1t);
    k_prep<<<(C1t * C2t + 255) / 256 + 1, 256>>>(W2, p_s1, p_q1, bn1g, bn1b,
                                                 nullptr, p_W2f, p_c2, C1t, C2t);
    k_gemm<<<dim3((Nn + 127) / 128, C2t / 128), 256>>>(p_h1, p_W2f, p_g2, C1t, C2t);
    k_agg<<<Nn, C2t>>>(p_g2, p_c2, b2, p_h2, C2t);

    k_stats<<<256, 128>>>(p_h2, p_s2, p_q2, C2t);
    k_prep<<<2, 256>>>(linW, p_s2, p_q2, bn2g, bn2b, linb, p_Wlf, p_c3, C2t, 2);
    k_final<<<(Nn + 7) / 8, 256>>>(out);
}

// round 11
// speedup vs baseline: 1.0583x; 1.0583x over previous
#include <cuda_runtime.h>

#define Nn   20000
#define PADR 128
#define Ee   640000
#define ENt  660000      // edges + self loops
#define INFt 2048
#define OMt  512
#define NCt  8192
#define C1t  256
#define C2t  128
#define EPSf 1e-5f

// ---------------- device scratch (static, no allocation) ----------------
__device__ int   g_ei64, g_sm64;
__device__ int   d_ROW[ENt], d_COL[ENt];
__device__ float d_deg[Nn], d_dinv[Nn];
__device__ int   d_ecnt[Nn], d_fillc[Nn], d_indptr[Nn + 1];
__device__ int   d_src[ENt];
__device__ float d_cw[ENt];
__device__ int   d_mcnt[OMt], d_mfill[OMt], d_mptr[OMt + 1];
__device__ int   d_min_[NCt], d_mout[NCt], d_sin[NCt];
__device__ float d_mw[NCt], d_sw[NCt];
__device__ float d_h0[(size_t)(Nn + PADR) * OMt];
__device__ float d_g1[(size_t)(Nn + PADR) * C1t], d_h1[(size_t)(Nn + PADR) * C1t];
__device__ float d_g2[(size_t)(Nn + PADR) * C2t], d_h2[(size_t)(Nn + PADR) * C2t];
__device__ float d_sum0[OMt], d_sq0[OMt], d_sum1[C1t], d_sq1[C1t], d_sum2[C2t], d_sq2[C2t];
__device__ float d_W1f[OMt * C1t], d_c1[C1t];
__device__ float d_W2f[C1t * C2t], d_c2[C2t];
__device__ float d_Wlf[C2t * 2],  d_c3[2];

// ---------------- 1: dtype sniff + zero mask counters ----------------
__global__ void k_detect(const unsigned* ei, const unsigned* sm) {
    __shared__ int f0, f1;
    int t = threadIdx.x;
    if (t == 0) { f0 = 0; f1 = 0; }
    __syncthreads();
    if (t < 128) {
        if (ei[2 * t + 1]) atomicOr(&f0, 1);
        if (sm[2 * t + 1]) atomicOr(&f1, 1);
    }
    for (int i = t; i < OMt; i += 128) { d_mcnt[i] = 0; d_mfill[i] = 0; }
    __syncthreads();
    if (t == 0) { g_ei64 = (f0 == 0); g_sm64 = (f1 == 0); }
}

// ---------------- 2: decode sparse mask + count per out column ----------------
__global__ void k_maskcount(const void* smv, const float* __restrict__ smw) {
    int j = blockIdx.x * blockDim.x + threadIdx.x;
    if (j >= NCt) return;
    int a, b;
    if (g_sm64) {
        const long long* p = (const long long*)smv;
        a = (int)p[2 * j]; b = (int)p[2 * j + 1];
    } else {
        const int* p = (const int*)smv;
        a = p[2 * j]; b = p[2 * j + 1];
    }
    d_min_[j] = a; d_mout[j] = b; d_mw[j] = smw[j];
    atomicAdd(&d_mcnt[b], 1);
}

// ---------------- 3: single block: scan 512 mask counts + CSC fill ----------------
__global__ void __launch_bounds__(512) k_mask_scanfill() {
    __shared__ int wsum[16];
    int t = threadIdx.x;
    int lane = t & 31, warp = t >> 5;
    int v = d_mcnt[t];
    int s = v;
#pragma unroll
    for (int off = 1; off < 32; off <<= 1) {
        int u = __shfl_up_sync(~0u, s, off);
        if (lane >= off) s += u;
    }
    if (lane == 31) wsum[warp] = s;
    __syncthreads();
    if (warp == 0 && lane < 16) {
        int w = wsum[lane];
#pragma unroll
        for (int off = 1; off < 16; off <<= 1) {
            int u = __shfl_up_sync(0xffffu, w, off);
            if (lane >= off) w += u;
        }
        wsum[lane] = w;
    }
    __syncthreads();
    int incl = s + (warp ? wsum[warp - 1] : 0);
    d_mptr[t] = incl - v;
    if (t == 511) d_mptr[OMt] = incl;
    __syncthreads();
    for (int j = t; j < NCt; j += 512) {
        int b = d_mout[j];
        int p = d_mptr[b] + atomicAdd(&d_mfill[b], 1);
        d_sin[p] = d_min_[j];
        d_sw[p] = d_mw[j];
    }
}

// ---------------- 4 (PROFILED): sparse masked linear + ReLU ----------------
#define NPB 4
__global__ void __launch_bounds__(512) k_stageA(const float* __restrict__ x,
                                                const float* __restrict__ smb) {
    __shared__ float4 xs4[INFt];
    int node0 = blockIdx.x * NPB;
    int t = threadIdx.x;
    const float* x0 = x + (size_t)node0 * INFt;
#pragma unroll
    for (int i = 0; i < INFt / 512; i++) {
        int f = t + i * 512;
        float4 v;
        v.x = __ldg(&x0[f]);
        v.y = __ldg(&x0[f + INFt]);
        v.z = __ldg(&x0[f + 2 * INFt]);
        v.w = __ldg(&x0[f + 3 * INFt]);
        xs4[f] = v;
    }
    __syncthreads();
    int o = t;
    float a0 = 0.f, a1 = 0.f, a2 = 0.f, a3 = 0.f;
    int p0 = d_mptr[o], p1 = d_mptr[o + 1];
    for (int p = p0; p < p1; p++) {
        int idx = d_sin[p];
        float w = d_sw[p];
        float4 v = xs4[idx];
        a0 += v.x * w;
        a1 += v.y * w;
        a2 += v.z * w;
        a3 += v.w * w;
    }
    float b = smb[o];
    d_h0[(size_t)(node0 + 0) * OMt + o] = fmaxf(a0 + b, 0.f);
    d_h0[(size_t)(node0 + 1) * OMt + o] = fmaxf(a1 + b, 0.f);
    d_h0[(size_t)(node0 + 2) * OMt + o] = fmaxf(a2 + b, 0.f);
    d_h0[(size_t)(node0 + 3) * OMt + o] = fmaxf(a3 + b, 0.f);
}

// ---------------- 5: zero edge counters + BN accumulators ----------------
__global__ void k_zero() {
    int i = blockIdx.x * blockDim.x + threadIdx.x;
    if (i < Nn)  { d_deg[i] = 0.f; d_ecnt[i] = 0; d_fillc[i] = 0; }
    if (i < OMt) { d_sum0[i] = 0.f; d_sq0[i] = 0.f; }
    if (i < C1t) { d_sum1[i] = 0.f; d_sq1[i] = 0.f; }
    if (i < C2t) { d_sum2[i] = 0.f; d_sq2[i] = 0.f; }
}

// ---------------- 6: decode edges + per-col degree/count ----------------
__global__ void k_edges(const void* eiv, const float* __restrict__ ew) {
    int e = blockIdx.x * blockDim.x + threadIdx.x;
    if (e >= ENt) return;
    int r, c;
    if (e < Ee) {
        if (g_ei64) {
            const long long* p = (const long long*)eiv;
            r = (int)p[e]; c = (int)p[Ee + e];
        } else {
            const int* p = (const int*)eiv;
            r = p[e]; c = p[Ee + e];
        }
    } else { r = c = e - Ee; }
    float w = (e < Ee) ? ew[e] : 1.f;
    d_ROW[e] = r; d_COL[e] = c;
    atomicAdd(&d_deg[c], w);
    atomicAdd(&d_ecnt[c], 1);
}

// ---------------- 7: shuffle-scan indptr (20000) + dinv ----------------
__global__ void __launch_bounds__(1024) k_scan_dinv() {
    __shared__ int wsum[32];
    const int CH = 20;
    int t = threadIdx.x;
    int lane = t & 31, warp = t >> 5;
    int base = t * CH;
    int cnts[CH];
    int loc = 0;
#pragma unroll
    for (int i = 0; i < CH; i++) {
        int v = (base + i < Nn) ? __ldg(&d_ecnt[base + i]) : 0;
        cnts[i] = v; loc += v;
    }
    int s = loc;
#pragma unroll
    for (int off = 1; off < 32; off <<= 1) {
        int u = __shfl_up_sync(~0u, s, off);
        if (lane >= off) s += u;
    }
    if (lane == 31) wsum[warp] = s;
    __syncthreads();
    if (warp == 0) {
        int w = wsum[lane];
#pragma unroll
        for (int off = 1; off < 32; off <<= 1) {
            int u = __shfl_up_sync(~0u, w, off);
            if (lane >= off) w += u;
        }
        wsum[lane] = w;
    }
    __syncthreads();
    int run = s - loc + (warp ? wsum[warp - 1] : 0);
#pragma unroll
    for (int i = 0; i < CH; i++) {
        if (base + i < Nn) d_indptr[base + i] = run;
        run += cnts[i];
    }
    if (t == 1023) d_indptr[Nn] = run;
    for (int i = t; i < Nn; i += 1024) {
        float dg = d_deg[i];
        d_dinv[i] = (dg > 0.f) ? rsqrtf(dg) : 0.f;
    }
}

// ---------------- 8: CSR fill with normalized weights ----------------
__global__ void k_fill(const float* __restrict__ ew) {
    int e = blockIdx.x * blockDim.x + threadIdx.x;
    if (e >= ENt) return;
    int c = d_COL[e], r = d_ROW[e];
    int p = d_indptr[c] + atomicAdd(&d_fillc[c], 1);
    float w = (e < Ee) ? ew[e] : 1.f;
    d_src[p] = r;
    d_cw[p] = d_dinv[r] * w * d_dinv[c];
}

// ---------------- column stats (low-contention: 256 blocks) ----------------
__global__ void k_stats(const float* __restrict__ in, float* __restrict__ sum,
                        float* __restrict__ sq, int F) {
    int t = threadIdx.x;   // blockDim == F
    float s = 0.f, q = 0.f;
    for (int r = blockIdx.x; r < Nn; r += gridDim.x) {
        float v = in[(size_t)r * F + t];
        s += v; q += v * v;
    }
    atomicAdd(&sum[t], s);
    atomicAdd(&sq[t], q);
}

// ---------------- merged BN-fold: Wf = a⊙W (rows), c = d@W (+addb) ----------------
__global__ void __launch_bounds__(256) k_prep(
    const float* __restrict__ W, const float* __restrict__ sum,
    const float* __restrict__ sq, const float* __restrict__ g,
    const float* __restrict__ b, const float* __restrict__ addb,
    float* __restrict__ Wf, float* __restrict__ cvec, int Kd, int Nd) {
    int t = threadIdx.x;
    if (blockIdx.x + 1 < gridDim.x) {
        int i = blockIdx.x * 256 + t;
        if (i < Kd * Nd) {
            int k = i / Nd;
            float m = sum[k] * (1.f / Nn);
            float v = fmaxf(sq[k] * (1.f / Nn) - m * m, 0.f);
            float s = g[k] * rsqrtf(v + EPSf);
            Wf[i] = s * W[i];
        }
    } else {
        __shared__ float dsh[512];
        for (int k = t; k < Kd; k += 256) {
            float m = sum[k] * (1.f / Nn);
            float v = fmaxf(sq[k] * (1.f / Nn) - m * m, 0.f);
            float s = g[k] * rsqrtf(v + EPSf);
            dsh[k] = b[k] - m * s;
        }
        __syncthreads();
        if (t < Nd) {
            float s = addb ? addb[t] : 0.f;
            for (int k = 0; k < Kd; k++) s += dsh[k] * W[k * Nd + t];
            cvec[t] = s;
        }
    }
}

// ---------------- fp32x2 packed SGEMM: C[M,Nd] = A[M,K]@B[K,Nd] ----------------
// 128x128 tile, 8x8 micro via 32 f32x2 accumulators (2 output cols per pair).
// A stored in smem as duplicated pairs: As2[k][2m] = As2[k][2m+1] = A[m][k],
// so the broadcast operand of fma.rn.f32x2 comes straight from an LDS.128.
// A, C padded to Nn+PADR rows -> no row guards.
__device__ __forceinline__ void fma2(unsigned long long& c, unsigned long long a,
                                     unsigned long long b) {
    asm("fma.rn.f32x2 %0, %1, %2, %0;" : "+l"(c) : "l"(a), "l"(b));
}

__global__ void __launch_bounds__(256, 2)
k_gemm(const float* __restrict__ A, const float* __restrict__ B,
       float* __restrict__ C, int K, int Nd) {
    __shared__ __align__(16) float As2[16][256];  // duplicated pairs
    __shared__ __align__(16) float Bs[16][128];
    int t = threadIdx.x;
    int tx = t & 15, ty = t >> 4;
    int mb = blockIdx.x * 128, nb = blockIdx.y * 128;
    unsigned long long c[8][4];
#pragma unroll
    for (int i = 0; i < 8; i++)
#pragma unroll
        for (int j = 0; j < 4; j++) c[i][j] = 0ull;

    for (int kt = 0; kt < K; kt += 16) {
#pragma unroll
        for (int i = 0; i < 2; i++) {
            int li = t + i * 256;
            int row = li >> 2, kq = li & 3;
            float4 v = *(const float4*)(A + (size_t)(mb + row) * K + kt + kq * 4);
            int kk = kq * 4;
            *(float2*)&As2[kk + 0][2 * row] = make_float2(v.x, v.x);
            *(float2*)&As2[kk + 1][2 * row] = make_float2(v.y, v.y);
            *(float2*)&As2[kk + 2][2 * row] = make_float2(v.z, v.z);
            *(float2*)&As2[kk + 3][2 * row] = make_float2(v.w, v.w);
        }
#pragma unroll
        for (int i = 0; i < 2; i++) {
            int li = t + i * 256;
            int kr = li >> 5, jq = li & 31;
            *(float4*)&Bs[kr][jq * 4] =
                *(const float4*)(B + (size_t)(kt + kr) * Nd + nb + jq * 4);
        }
        __syncthreads();
#pragma unroll
        for (int k = 0; k < 16; k++) {
            ulonglong2 A0 = *(const ulonglong2*)&As2[k][ty * 16];
            ulonglong2 A1 = *(const ulonglong2*)&As2[k][ty * 16 + 4];
            ulonglong2 A2 = *(const ulonglong2*)&As2[k][ty * 16 + 8];
            ulonglong2 A3 = *(const ulonglong2*)&As2[k][ty * 16 + 12];
            ulonglong2 B0 = *(const ulonglong2*)&Bs[k][tx * 8];
            ulonglong2 B1 = *(const ulonglong2*)&Bs[k][tx * 8 + 4];
            unsigned long long av[8] = {A0.x, A0.y, A1.x, A1.y, A2.x, A2.y, A3.x, A3.y};
            unsigned long long bv[4] = {B0.x, B0.y, B1.x, B1.y};
#pragma unroll
            for (int i = 0; i < 8; i++)
#pragma unroll
                for (int j = 0; j < 4; j++) fma2(c[i][j], av[i], bv[j]);
        }
        __syncthreads();
    }
#pragma unroll
    for (int i = 0; i < 8; i++) {
        int m = mb + ty * 8 + i;
#pragma unroll
        for (int j = 0; j < 4; j++) {
            int col = nb + tx * 8 + j * 2;
            *(float2*)(C + (size_t)m * Nd + col) = *(float2*)&c[i][j];
        }
    }
}

// ---------------- CSR agg: out[n] = relu(sum w*g[src] + (sum w)*cv + bias) ----------------
__global__ void k_agg(const float* __restrict__ g, const float* __restrict__ cv,
                      const float* __restrict__ bias, float* __restrict__ out, int F) {
    int n = blockIdx.x, t = threadIdx.x;
    int s0 = d_indptr[n], s1 = d_indptr[n + 1];
    float acc = 0.f, ws = 0.f;
    for (int e = s0; e < s1; e++) {
        int s = __ldg(&d_src[e]);
        float w = __ldg(&d_cw[e]);
        ws += w;
        acc += g[(size_t)s * F + t] * w;
    }
    out[(size_t)n * F + t] = fmaxf(acc + ws * cv[t] + bias[t], 0.f);
}

// ---------------- final linear: out[n,:2] = h2[n,:] @ Wlf + c3 ----------------
__global__ void k_final(float* __restrict__ out) {
    int w = blockIdx.x * 8 + (threadIdx.x >> 5);
    int lane = threadIdx.x & 31;
    if (w >= Nn) return;
    float4 v = ((const float4*)(d_h2 + (size_t)w * C2t))[lane];
    float4 w0 = ((const float4*)d_Wlf)[lane * 2];
    float4 w1 = ((const float4*)d_Wlf)[lane * 2 + 1];
    float s0 = v.x * w0.x + v.y * w0.z + v.z * w1.x + v.w * w1.z;
    float s1 = v.x * w0.y + v.y * w0.w + v.z * w1.y + v.w * w1.w;
#pragma unroll
    for (int off = 16; off; off >>= 1) {
        s0 += __shfl_down_sync(0xffffffffu, s0, off);
        s1 += __shfl_down_sync(0xffffffffu, s1, off);
    }
    if (lane == 0) {
        out[w * 2 + 0] = s0 + d_c3[0];
        out[w * 2 + 1] = s1 + d_c3[1];
    }
}

// ---------------- host launch ----------------
extern "C" void kernel_launch(void* const* d_in, const int* in_sizes, int n_in,
                              void* d_out, int out_size) {
    const float* x     = (const float*)d_in[0];
    const void*  ei    = d_in[1];
    const float* ew    = (const float*)d_in[2];
    const void*  sm    = d_in[3];
    const float* smw   = (const float*)d_in[4];
    const float* smb   = (const float*)d_in[5];
    const float* bnsg  = (const float*)d_in[6];
    const float* bnsb  = (const float*)d_in[7];
    const float* W1    = (const float*)d_in[8];
    const float* b1    = (const float*)d_in[9];
    const float* bn1g  = (const float*)d_in[10];
    const float* bn1b  = (const float*)d_in[11];
    const float* W2    = (const float*)d_in[12];
    const float* b2    = (const float*)d_in[13];
    const float* bn2g  = (const float*)d_in[14];
    const float* bn2b  = (const float*)d_in[15];
    const float* linW  = (const float*)d_in[16];
    const float* linb  = (const float*)d_in[17];
    float* out = (float*)d_out;

    float *p_h0, *p_g1, *p_h1, *p_g2, *p_h2;
    float *p_W1f, *p_W2f, *p_Wlf, *p_c1, *p_c2, *p_c3;
    float *p_s0, *p_q0, *p_s1, *p_q1, *p_s2, *p_q2;
    cudaGetSymbolAddress((void**)&p_h0, d_h0);
    cudaGetSymbolAddress((void**)&p_g1, d_g1);
    cudaGetSymbolAddress((void**)&p_h1, d_h1);
    cudaGetSymbolAddress((void**)&p_g2, d_g2);
    cudaGetSymbolAddress((void**)&p_h2, d_h2);
    cudaGetSymbolAddress((void**)&p_W1f, d_W1f);
    cudaGetSymbolAddress((void**)&p_W2f, d_W2f);
    cudaGetSymbolAddress((void**)&p_Wlf, d_Wlf);
    cudaGetSymbolAddress((void**)&p_c1, d_c1);
    cudaGetSymbolAddress((void**)&p_c2, d_c2);
    cudaGetSymbolAddress((void**)&p_c3, d_c3);
    cudaGetSymbolAddress((void**)&p_s0, d_sum0);
    cudaGetSymbolAddress((void**)&p_q0, d_sq0);
    cudaGetSymbolAddress((void**)&p_s1, d_sum1);
    cudaGetSymbolAddress((void**)&p_q1, d_sq1);
    cudaGetSymbolAddress((void**)&p_s2, d_sum2);
    cudaGetSymbolAddress((void**)&p_q2, d_sq2);

    k_detect<<<1, 128>>>((const unsigned*)ei, (const unsigned*)sm);    // 1
    k_maskcount<<<32, 256>>>(sm, smw);                                 // 2
    k_mask_scanfill<<<1, 512>>>();                                     // 3
    k_stageA<<<Nn / NPB, 512>>>(x, smb);                               // 4 <- ncu capture
    k_zero<<<(Nn + 255) / 256, 256>>>();                               // 5
    k_edges<<<(ENt + 255) / 256, 256>>>(ei, ew);                       // 6
    k_scan_dinv<<<1, 1024>>>();                                        // 7
    k_fill<<<(ENt + 255) / 256, 256>>>(ew);                            // 8

    k_stats<<<256, 512>>>(p_h0, p_s0, p_q0, OMt);                      // 9
    k_prep<<<(OMt * C1t + 255) / 256 + 1, 256>>>(W1, p_s0, p_q0, bnsg, bnsb,
                                                 nullptr, p_W1f, p_c1, OMt, C1t);
    k_gemm<<<dim3((Nn + 127) / 128, C1t / 128), 256>>>(p_h0, p_W1f, p_g1, OMt, C1t);
    k_agg<<<Nn, C1t>>>(p_g1, p_c1, b1, p_h1, C1t);

    k_stats<<<256, 256>>>(p_h1, p_s1, p_q1, C1t);
    k_prep<<<(C1t * C2t + 255) / 256 + 1, 256>>>(W2, p_s1, p_q1, bn1g, bn1b,
                                                 nullptr, p_W2f, p_c2, C1t, C2t);
    k_gemm<<<dim3((Nn + 127) / 128, C2t / 128), 256>>>(p_h1, p_W2f, p_g2, C1t, C2t);
    k_agg<<<Nn, C2t>>>(p_g2, p_c2, b2, p_h2, C2t);

    k_stats<<<256, 128>>>(p_h2, p_s2, p_q2, C2t);
    k_prep<<<2, 256>>>(linW, p_s2, p_q2, bn2g, bn2b, linb, p_Wlf, p_c3, C2t, 2);
    k_final<<<(Nn + 7) / 8, 256>>>(out);
}

// round 15
// speedup vs baseline: 1.4221x; 1.3438x over previous
#include <cuda_runtime.h>
#include <cuda_bf16.h>
#include <cstdint>

#define Nn   20000
#define PADR 128
#define Ee   640000
#define ENt  660000      // edges + self loops
#define INFt 2048
#define OMt  512
#define NCt  8192
#define C1t  256
#define C2t  128
#define EPSf 1e-5f

// ---------------- device scratch (static, no allocation) ----------------
__device__ int   g_ei64, g_sm64;
__device__ int   d_ROW[ENt], d_COL[ENt];
__device__ float d_deg[Nn], d_dinv[Nn];
__device__ int   d_ecnt[Nn], d_fillc[Nn], d_indptr[Nn + 1];
__device__ int   d_src[ENt];
__device__ float d_cw[ENt];
__device__ int   d_mcnt[OMt], d_mfill[OMt], d_mptr[OMt + 1];
__device__ int   d_min_[NCt], d_mout[NCt], d_sin[NCt];
__device__ float d_mw[NCt], d_sw[NCt];
__device__ float d_h0[(size_t)(Nn + PADR) * OMt];
__device__ float d_g1[(size_t)(Nn + PADR) * C1t], d_h1[(size_t)(Nn + PADR) * C1t];
__device__ float d_g2[(size_t)(Nn + PADR) * C2t], d_h2[(size_t)(Nn + PADR) * C2t];
// bf16 split operands for mma.sync GEMMs (pad rows stay zero-initialized)
__device__ __align__(16) __nv_bfloat16 d_h0h[(size_t)(Nn + PADR) * OMt];
__device__ __align__(16) __nv_bfloat16 d_h0l[(size_t)(Nn + PADR) * OMt];
__device__ __align__(16) __nv_bfloat16 d_h1h[(size_t)(Nn + PADR) * C1t];
__device__ __align__(16) __nv_bfloat16 d_h1l[(size_t)(Nn + PADR) * C1t];
__device__ __align__(16) __nv_bfloat16 d_W1th[C1t * OMt], d_W1tl[C1t * OMt]; // [N][K]
__device__ __align__(16) __nv_bfloat16 d_W2th[C2t * C1t], d_W2tl[C2t * C1t]; // [N][K]
__device__ float d_sum0[OMt], d_sq0[OMt], d_sum1[C1t], d_sq1[C1t], d_sum2[C2t], d_sq2[C2t];
__device__ float d_W1f[OMt * C1t], d_c1[C1t];
__device__ float d_W2f[C1t * C2t], d_c2[C2t];
__device__ float d_Wlf[C2t * 2],  d_c3[2];

__device__ __forceinline__ void bf16split(float v, __nv_bfloat16& h, __nv_bfloat16& l) {
    h = __float2bfloat16(v);
    l = __float2bfloat16(v - __bfloat162float(h));
}

// ---------------- mma.sync helpers (sm_80+, valid on sm_100 base) ----------------
__device__ __forceinline__ void ldsm4(uint32_t* r, uint32_t addr) {
    asm volatile("ldmatrix.sync.aligned.m8n8.x4.shared.b16 {%0,%1,%2,%3}, [%4];"
                 : "=r"(r[0]), "=r"(r[1]), "=r"(r[2]), "=r"(r[3]) : "r"(addr));
}
__device__ __forceinline__ void mma16816(float* d, const uint32_t* a, const uint32_t* b) {
    asm volatile(
        "mma.sync.aligned.m16n8k16.row.col.f32.bf16.bf16.f32 "
        "{%0,%1,%2,%3}, {%4,%5,%6,%7}, {%8,%9}, {%0,%1,%2,%3};"
        : "+f"(d[0]), "+f"(d[1]), "+f"(d[2]), "+f"(d[3])
        : "r"(a[0]), "r"(a[1]), "r"(a[2]), "r"(a[3]), "r"(b[0]), "r"(b[1]));
}

// ---------------- 1: dtype sniff + zero mask counters ----------------
__global__ void k_detect(const unsigned* ei, const unsigned* sm) {
    __shared__ int f0, f1;
    int t = threadIdx.x;
    if (t == 0) { f0 = 0; f1 = 0; }
    __syncthreads();
    if (t < 128) {
        if (ei[2 * t + 1]) atomicOr(&f0, 1);
        if (sm[2 * t + 1]) atomicOr(&f1, 1);
    }
    for (int i = t; i < OMt; i += 128) { d_mcnt[i] = 0; d_mfill[i] = 0; }
    __syncthreads();
    if (t == 0) { g_ei64 = (f0 == 0); g_sm64 = (f1 == 0); }
}

// ---------------- 2: decode sparse mask + count per out column ----------------
__global__ void k_maskcount(const void* smv, const float* __restrict__ smw) {
    int j = blockIdx.x * blockDim.x + threadIdx.x;
    if (j >= NCt) return;
    int a, b;
    if (g_sm64) {
        const long long* p = (const long long*)smv;
        a = (int)p[2 * j]; b = (int)p[2 * j + 1];
    } else {
        const int* p = (const int*)smv;
        a = p[2 * j]; b = p[2 * j + 1];
    }
    d_min_[j] = a; d_mout[j] = b; d_mw[j] = smw[j];
    atomicAdd(&d_mcnt[b], 1);
}

// ---------------- 3: single block: scan 512 mask counts + CSC fill ----------------
__global__ void __launch_bounds__(512) k_mask_scanfill() {
    __shared__ int wsum[16];
    int t = threadIdx.x;
    int lane = t & 31, warp = t >> 5;
    int v = d_mcnt[t];
    int s = v;
#pragma unroll
    for (int off = 1; off < 32; off <<= 1) {
        int u = __shfl_up_sync(~0u, s, off);
        if (lane >= off) s += u;
    }
    if (lane == 31) wsum[warp] = s;
    __syncthreads();
    if (warp == 0 && lane < 16) {
        int w = wsum[lane];
#pragma unroll
        for (int off = 1; off < 16; off <<= 1) {
            int u = __shfl_up_sync(0xffffu, w, off);
            if (lane >= off) w += u;
        }
        wsum[lane] = w;
    }
    __syncthreads();
    int incl = s + (warp ? wsum[warp - 1] : 0);
    d_mptr[t] = incl - v;
    if (t == 511) d_mptr[OMt] = incl;
    __syncthreads();
    for (int j = t; j < NCt; j += 512) {
        int b = d_mout[j];
        int p = d_mptr[b] + atomicAdd(&d_mfill[b], 1);
        d_sin[p] = d_min_[j];
        d_sw[p] = d_mw[j];
    }
}

// ---------------- 4 (PROFILED): sparse masked linear + ReLU + bf16 split out ----------------
#define NPB 4
__global__ void __launch_bounds__(512) k_stageA(const float* __restrict__ x,
                                                const float* __restrict__ smb) {
    __shared__ float4 xs4[INFt];
    int node0 = blockIdx.x * NPB;
    int t = threadIdx.x;
    const float* x0 = x + (size_t)node0 * INFt;
#pragma unroll
    for (int i = 0; i < INFt / 512; i++) {
        int f = t + i * 512;
        float4 v;
        v.x = __ldg(&x0[f]);
        v.y = __ldg(&x0[f + INFt]);
        v.z = __ldg(&x0[f + 2 * INFt]);
        v.w = __ldg(&x0[f + 3 * INFt]);
        xs4[f] = v;
    }
    __syncthreads();
    int o = t;
    float a0 = 0.f, a1 = 0.f, a2 = 0.f, a3 = 0.f;
    int p0 = d_mptr[o], p1 = d_mptr[o + 1];
    for (int p = p0; p < p1; p++) {
        int idx = d_sin[p];
        float w = d_sw[p];
        float4 v = xs4[idx];
        a0 += v.x * w;
        a1 += v.y * w;
        a2 += v.z * w;
        a3 += v.w * w;
    }
    float b = smb[o];
    float vv[4] = {fmaxf(a0 + b, 0.f), fmaxf(a1 + b, 0.f),
                   fmaxf(a2 + b, 0.f), fmaxf(a3 + b, 0.f)};
#pragma unroll
    for (int i = 0; i < 4; i++) {
        size_t off = (size_t)(node0 + i) * OMt + o;
        d_h0[off] = vv[i];
        __nv_bfloat16 h, l;
        bf16split(vv[i], h, l);
        d_h0h[off] = h;
        d_h0l[off] = l;
    }
}

// ---------------- 5: zero edge counters + BN accumulators ----------------
__global__ void k_zero() {
    int i = blockIdx.x * blockDim.x + threadIdx.x;
    if (i < Nn)  { d_deg[i] = 0.f; d_ecnt[i] = 0; d_fillc[i] = 0; }
    if (i < OMt) { d_sum0[i] = 0.f; d_sq0[i] = 0.f; }
    if (i < C1t) { d_sum1[i] = 0.f; d_sq1[i] = 0.f; }
    if (i < C2t) { d_sum2[i] = 0.f; d_sq2[i] = 0.f; }
}

// ---------------- 6: decode edges + per-col degree/count ----------------
__global__ void k_edges(const void* eiv, const float* __restrict__ ew) {
    int e = blockIdx.x * blockDim.x + threadIdx.x;
    if (e >= ENt) return;
    int r, c;
    if (e < Ee) {
        if (g_ei64) {
            const long long* p = (const long long*)eiv;
            r = (int)p[e]; c = (int)p[Ee + e];
        } else {
            const int* p = (const int*)eiv;
            r = p[e]; c = p[Ee + e];
        }
    } else { r = c = e - Ee; }
    float w = (e < Ee) ? ew[e] : 1.f;
    d_ROW[e] = r; d_COL[e] = c;
    atomicAdd(&d_deg[c], w);
    atomicAdd(&d_ecnt[c], 1);
}

// ---------------- 7: shuffle-scan indptr (20000) + dinv ----------------
__global__ void __launch_bounds__(1024) k_scan_dinv() {
    __shared__ int wsum[32];
    const int CH = 20;
    int t = threadIdx.x;
    int lane = t & 31, warp = t >> 5;
    int base = t * CH;
    int cnts[CH];
    int loc = 0;
#pragma unroll
    for (int i = 0; i < CH; i++) {
        int v = (base + i < Nn) ? __ldg(&d_ecnt[base + i]) : 0;
        cnts[i] = v; loc += v;
    }
    int s = loc;
#pragma unroll
    for (int off = 1; off < 32; off <<= 1) {
        int u = __shfl_up_sync(~0u, s, off);
        if (lane >= off) s += u;
    }
    if (lane == 31) wsum[warp] = s;
    __syncthreads();
    if (warp == 0) {
        int w = wsum[lane];
#pragma unroll
        for (int off = 1; off < 32; off <<= 1) {
            int u = __shfl_up_sync(~0u, w, off);
            if (lane >= off) w += u;
        }
        wsum[lane] = w;
    }
    __syncthreads();
    int run = s - loc + (warp ? wsum[warp - 1] : 0);
#pragma unroll
    for (int i = 0; i < CH; i++) {
        if (base + i < Nn) d_indptr[base + i] = run;
        run += cnts[i];
    }
    if (t == 1023) d_indptr[Nn] = run;
    for (int i = t; i < Nn; i += 1024) {
        float dg = d_deg[i];
        d_dinv[i] = (dg > 0.f) ? rsqrtf(dg) : 0.f;
    }
}

// ---------------- 8: CSR fill with normalized weights ----------------
__global__ void k_fill(const float* __restrict__ ew) {
    int e = blockIdx.x * blockDim.x + threadIdx.x;
    if (e >= ENt) return;
    int c = d_COL[e], r = d_ROW[e];
    int p = d_indptr[c] + atomicAdd(&d_fillc[c], 1);
    float w = (e < Ee) ? ew[e] : 1.f;
    d_src[p] = r;
    d_cw[p] = d_dinv[r] * w * d_dinv[c];
}

// ---------------- column stats (low-contention: 256 blocks) ----------------
__global__ void k_stats(const float* __restrict__ in, float* __restrict__ sum,
                        float* __restrict__ sq, int F) {
    int t = threadIdx.x;   // blockDim == F
    float s = 0.f, q = 0.f;
    for (int r = blockIdx.x; r < Nn; r += gridDim.x) {
        float v = in[(size_t)r * F + t];
        s += v; q += v * v;
    }
    atomicAdd(&sum[t], s);
    atomicAdd(&sq[t], q);
}

// ---------------- BN-fold: Wf = a⊙W, transposed bf16 hi/lo, c = d@W (+addb) ----------------
__global__ void __launch_bounds__(256) k_prep(
    const float* __restrict__ W, const float* __restrict__ sum,
    const float* __restrict__ sq, const float* __restrict__ g,
    const float* __restrict__ b, const float* __restrict__ addb,
    float* __restrict__ Wf, __nv_bfloat16* __restrict__ Wth,
    __nv_bfloat16* __restrict__ Wtl, float* __restrict__ cvec, int Kd, int Nd) {
    int t = threadIdx.x;
    if (blockIdx.x + 1 < gridDim.x) {
        int i = blockIdx.x * 256 + t;
        if (i < Kd * Nd) {
            int k = i / Nd, n = i - k * Nd;
            float m = sum[k] * (1.f / Nn);
            float v = fmaxf(sq[k] * (1.f / Nn) - m * m, 0.f);
            float s = g[k] * rsqrtf(v + EPSf);
            float w = s * W[i];
            Wf[i] = w;
            if (Wth) {
                __nv_bfloat16 h, l;
                bf16split(w, h, l);
                Wth[n * Kd + k] = h;
                Wtl[n * Kd + k] = l;
            }
        }
    } else {
        __shared__ float dsh[512];
        for (int k = t; k < Kd; k += 256) {
            float m = sum[k] * (1.f / Nn);
            float v = fmaxf(sq[k] * (1.f / Nn) - m * m, 0.f);
            float s = g[k] * rsqrtf(v + EPSf);
            dsh[k] = b[k] - m * s;
        }
        __syncthreads();
        if (t < Nd) {
            float s = addb ? addb[t] : 0.f;
            for (int k = 0; k < Kd; k++) s += dsh[k] * W[k * Nd + t];
            cvec[t] = s;
        }
    }
}

// ---------------- bf16-split mma.sync GEMM: C[M,N] = A[M,K] @ Bt[N,K]^T ----------------
// Block 128Mx128N, 8 warps (2x4), warp tile 64x32 (4x4 m16n8 tiles), K-chunk 64.
// smem rows padded to 72 bf16 (144B) -> ldmatrix conflict-free.
#define KC  64
#define LDE 72
__global__ void __launch_bounds__(256) k_gemm_mma(
    const __nv_bfloat16* __restrict__ Ah, const __nv_bfloat16* __restrict__ Al,
    const __nv_bfloat16* __restrict__ Bh, const __nv_bfloat16* __restrict__ Bl,
    float* __restrict__ C, int K, int N) {
    extern __shared__ __align__(16) __nv_bfloat16 sm[];
    __nv_bfloat16* sAh = sm;
    __nv_bfloat16* sAl = sm + 128 * LDE;
    __nv_bfloat16* sBh = sm + 2 * 128 * LDE;
    __nv_bfloat16* sBl = sm + 3 * 128 * LDE;
    uint32_t base_sa = (uint32_t)__cvta_generic_to_shared(sAh);
    uint32_t base_sb = (uint32_t)__cvta_generic_to_shared(sBh);
    const uint32_t LOFF = 128 * LDE * 2;   // bytes between hi and lo arrays

    int t = threadIdx.x;
    int warp = t >> 5, lane = t & 31;
    int wm = warp & 1, wn = warp >> 1;     // 2 x 4 warp grid
    int mb = blockIdx.x * 128, nb = blockIdx.y * 128;

    float acc[4][4][4];
#pragma unroll
    for (int i = 0; i < 4; i++)
#pragma unroll
        for (int j = 0; j < 4; j++)
#pragma unroll
            for (int e = 0; e < 4; e++) acc[i][j][e] = 0.f;

    // per-lane ldmatrix byte offsets (within a tile, relative to array base)
    int a_r = lane & 15, a_c8 = lane >> 4;          // A: row 0..15, k-half
    int b_r = ((lane >> 4) << 3) + (lane & 7);      // B: 8*(lane>>4) + lane&7
    int b_c8 = (lane >> 3) & 1;                     // B: k-half

    for (int kt = 0; kt < K; kt += KC) {
        // fill smem: 128 rows x 64 bf16 per array (8 uint4 per row)
        for (int i = t; i < 1024; i += 256) {
            int row = i >> 3, u = i & 7;
            size_t goA = (size_t)(mb + row) * K + kt + u * 8;
            size_t goB = (size_t)(nb + row) * K + kt + u * 8;
            int so = row * LDE + u * 8;
            *(uint4*)(sAh + so) = *(const uint4*)(Ah + goA);
            *(uint4*)(sAl + so) = *(const uint4*)(Al + goA);
            *(uint4*)(sBh + so) = *(const uint4*)(Bh + goB);
            *(uint4*)(sBl + so) = *(const uint4*)(Bl + goB);
        }
        __syncthreads();
#pragma unroll
        for (int ks = 0; ks < KC; ks += 16) {
            uint32_t aH[4][4], aL[4][4];
#pragma unroll
            for (int mi = 0; mi < 4; mi++) {
                uint32_t off = (uint32_t)((wm * 64 + mi * 16 + a_r) * LDE +
                                          ks + a_c8 * 8) * 2;
                ldsm4(aH[mi], base_sa + off);
                ldsm4(aL[mi], base_sa + LOFF + off);
            }
            uint32_t bH[4][2], bL[4][2];
#pragma unroll
            for (int np = 0; np < 2; np++) {
                uint32_t off = (uint32_t)((wn * 32 + np * 16 + b_r) * LDE +
                                          ks + b_c8 * 8) * 2;
                uint32_t rh[4], rl[4];
                ldsm4(rh, base_sb + off);
                ldsm4(rl, base_sb + LOFF + off);
                bH[np * 2][0] = rh[0]; bH[np * 2][1] = rh[1];
                bH[np * 2 + 1][0] = rh[2]; bH[np * 2 + 1][1] = rh[3];
                bL[np * 2][0] = rl[0]; bL[np * 2][1] = rl[1];
                bL[np * 2 + 1][0] = rl[2]; bL[np * 2 + 1][1] = rl[3];
            }
#pragma unroll
            for (int mi = 0; mi < 4; mi++)
#pragma unroll
                for (int ni = 0; ni < 4; ni++) {
                    mma16816(acc[mi][ni], aH[mi], bH[ni]);
                    mma16816(acc[mi][ni], aL[mi], bH[ni]);
                    mma16816(acc[mi][ni], aH[mi], bL[ni]);
                }
        }
        __syncthreads();
    }
    // store: d0,d1 -> (row, col..col+1); d2,d3 -> (row+8, col..col+1)
#pragma unroll
    for (int mi = 0; mi < 4; mi++) {
        int row = mb + wm * 64 + mi * 16 + (lane >> 2);
#pragma unroll
        for (int ni = 0; ni < 4; ni++) {
            int col = nb + wn * 32 + ni * 8 + (lane & 3) * 2;
            *(float2*)(C + (size_t)row * N + col) =
                make_float2(acc[mi][ni][0], acc[mi][ni][1]);
            *(float2*)(C + (size_t)(row + 8) * N + col) =
                make_float2(acc[mi][ni][2], acc[mi][ni][3]);
        }
    }
}

// ---------------- CSR agg: out = relu(sum w*g[src] + (sum w)*cv + bias) (+ bf16 split) ----------------
__global__ void k_agg(const float* __restrict__ g, const float* __restrict__ cv,
                      const float* __restrict__ bias, float* __restrict__ out,
                      __nv_bfloat16* __restrict__ oh, __nv_bfloat16* __restrict__ ol,
                      int F) {
    int n = blockIdx.x, t = threadIdx.x;
    int s0 = d_indptr[n], s1 = d_indptr[n + 1];
    float acc = 0.f, ws = 0.f;
    for (int e = s0; e < s1; e++) {
        int s = __ldg(&d_src[e]);
        float w = __ldg(&d_cw[e]);
        ws += w;
        acc += g[(size_t)s * F + t] * w;
    }
    float v = fmaxf(acc + ws * cv[t] + bias[t], 0.f);
    size_t off = (size_t)n * F + t;
    out[off] = v;
    if (oh) {
        __nv_bfloat16 h, l;
        bf16split(v, h, l);
        oh[off] = h;
        ol[off] = l;
    }
}

// ---------------- final linear: out[n,:2] = h2[n,:] @ Wlf + c3 ----------------
__global__ void k_final(float* __restrict__ out) {
    int w = blockIdx.x * 8 + (threadIdx.x >> 5);
    int lane = threadIdx.x & 31;
    if (w >= Nn) return;
    float4 v = ((const float4*)(d_h2 + (size_t)w * C2t))[lane];
    float4 w0 = ((const float4*)d_Wlf)[lane * 2];
    float4 w1 = ((const float4*)d_Wlf)[lane * 2 + 1];
    float s0 = v.x * w0.x + v.y * w0.z + v.z * w1.x + v.w * w1.z;
    float s1 = v.x * w0.y + v.y * w0.w + v.z * w1.y + v.w * w1.w;
#pragma unroll
    for (int off = 16; off; off >>= 1) {
        s0 += __shfl_down_sync(0xffffffffu, s0, off);
        s1 += __shfl_down_sync(0xffffffffu, s1, off);
    }
    if (lane == 0) {
        out[w * 2 + 0] = s0 + d_c3[0];
        out[w * 2 + 1] = s1 + d_c3[1];
    }
}

// ---------------- host launch ----------------
extern "C" void kernel_launch(void* const* d_in, const int* in_sizes, int n_in,
                              void* d_out, int out_size) {
    const float* x     = (const float*)d_in[0];
    const void*  ei    = d_in[1];
    const float* ew    = (const float*)d_in[2];
    const void*  sm    = d_in[3];
    const float* smw   = (const float*)d_in[4];
    const float* smb   = (const float*)d_in[5];
    const float* bnsg  = (const float*)d_in[6];
    const float* bnsb  = (const float*)d_in[7];
    const float* W1    = (const float*)d_in[8];
    const float* b1    = (const float*)d_in[9];
    const float* bn1g  = (const float*)d_in[10];
    const float* bn1b  = (const float*)d_in[11];
    const float* W2    = (const float*)d_in[12];
    const float* b2    = (const float*)d_in[13];
    const float* bn2g  = (const float*)d_in[14];
    const float* bn2b  = (const float*)d_in[15];
    const float* linW  = (const float*)d_in[16];
    const float* linb  = (const float*)d_in[17];
    float* out = (float*)d_out;

    float *p_h0, *p_g1, *p_h1, *p_g2, *p_h2;
    float *p_W1f, *p_W2f, *p_Wlf, *p_c1, *p_c2, *p_c3;
    float *p_s0, *p_q0, *p_s1, *p_q1, *p_s2, *p_q2;
    __nv_bfloat16 *p_h0h, *p_h0l, *p_h1h, *p_h1l;
    __nv_bfloat16 *p_W1th, *p_W1tl, *p_W2th, *p_W2tl;
    cudaGetSymbolAddress((void**)&p_h0, d_h0);
    cudaGetSymbolAddress((void**)&p_g1, d_g1);
    cudaGetSymbolAddress((void**)&p_h1, d_h1);
    cudaGetSymbolAddress((void**)&p_g2, d_g2);
    cudaGetSymbolAddress((void**)&p_h2, d_h2);
    cudaGetSymbolAddress((void**)&p_W1f, d_W1f);
    cudaGetSymbolAddress((void**)&p_W2f, d_W2f);
    cudaGetSymbolAddress((void**)&p_Wlf, d_Wlf);
    cudaGetSymbolAddress((void**)&p_c1, d_c1);
    cudaGetSymbolAddress((void**)&p_c2, d_c2);
    cudaGetSymbolAddress((void**)&p_c3, d_c3);
    cudaGetSymbolAddress((void**)&p_s0, d_sum0);
    cudaGetSymbolAddress((void**)&p_q0, d_sq0);
    cudaGetSymbolAddress((void**)&p_s1, d_sum1);
    cudaGetSymbolAddress((void**)&p_q1, d_sq1);
    cudaGetSymbolAddress((void**)&p_s2, d_sum2);
    cudaGetSymbolAddress((void**)&p_q2, d_sq2);
    cudaGetSymbolAddress((void**)&p_h0h, d_h0h);
    cudaGetSymbolAddress((void**)&p_h0l, d_h0l);
    cudaGetSymbolAddress((void**)&p_h1h, d_h1h);
    cudaGetSymbolAddress((void**)&p_h1l, d_h1l);
    cudaGetSymbolAddress((void**)&p_W1th, d_W1th);
    cudaGetSymbolAddress((void**)&p_W1tl, d_W1tl);
    cudaGetSymbolAddress((void**)&p_W2th, d_W2th);
    cudaGetSymbolAddress((void**)&p_W2tl, d_W2tl);

    const int GSM = 4 * 128 * LDE * 2;   // 73728 bytes
    cudaFuncSetAttribute(k_gemm_mma, cudaFuncAttributeMaxDynamicSharedMemorySize, GSM);

    k_detect<<<1, 128>>>((const unsigned*)ei, (const unsigned*)sm);    // 1
    k_maskcount<<<32, 256>>>(sm, smw);                                 // 2
    k_mask_scanfill<<<1, 512>>>();                                     // 3
    k_stageA<<<Nn / NPB, 512>>>(x, smb);                               // 4 <- ncu capture
    k_zero<<<(Nn + 255) / 256, 256>>>();                               // 5
    k_edges<<<(ENt + 255) / 256, 256>>>(ei, ew);                       // 6
    k_scan_dinv<<<1, 1024>>>();                                        // 7
    k_fill<<<(ENt + 255) / 256, 256>>>(ew);                            // 8

    k_stats<<<256, 512>>>(p_h0, p_s0, p_q0, OMt);                      // 9
    k_prep<<<(OMt * C1t + 255) / 256 + 1, 256>>>(W1, p_s0, p_q0, bnsg, bnsb,
                                                 nullptr, p_W1f, p_W1th, p_W1tl,
                                                 p_c1, OMt, C1t);
    k_gemm_mma<<<dim3((Nn + 127) / 128, C1t / 128), 256, GSM>>>(
        p_h0h, p_h0l, p_W1th, p_W1tl, p_g1, OMt, C1t);
    k_agg<<<Nn, C1t>>>(p_g1, p_c1, b1, p_h1, p_h1h, p_h1l, C1t);

    k_stats<<<256, 256>>>(p_h1, p_s1, p_q1, C1t);
    k_prep<<<(C1t * C2t + 255) / 256 + 1, 256>>>(W2, p_s1, p_q1, bn1g, bn1b,
                                                 nullptr, p_W2f, p_W2th, p_W2tl,
                                                 p_c2, C1t, C2t);
    k_gemm_mma<<<dim3((Nn + 127) / 128, C2t / 128), 256, GSM>>>(
        p_h1h, p_h1l, p_W2th, p_W2tl, p_g2, C1t, C2t);
    k_agg<<<Nn, C2t>>>(p_g2, p_c2, b2, p_h2, nullptr, nullptr, C2t);

    k_stats<<<256, 128>>>(p_h2, p_s2, p_q2, C2t);
    k_prep<<<2, 256>>>(linW, p_s2, p_q2, bn2g, bn2b, linb, p_Wlf,
                       nullptr, nullptr, p_c3, C2t, 2);
    k_final<<<(Nn + 7) / 8, 256>>>(out);
}

// round 16
// speedup vs baseline: 1.5743x; 1.1071x over previous
#include <cuda_runtime.h>
#include <cuda_bf16.h>
#include <cstdint>

#define Nn   20000
#define PADR 128
#define Ee   640000
#define ENt  660000      // edges + self loops
#define INFt 2048
#define OMt  512
#define NCt  8192
#define C1t  256
#define C2t  128
#define EPSf 1e-5f

// ---------------- device scratch (static, no allocation) ----------------
__device__ int   g_ei64, g_sm64;
__device__ int   d_ROW[ENt], d_COL[ENt];
__device__ float d_deg[Nn], d_dinv[Nn];
__device__ int   d_ecnt[Nn], d_fillc[Nn], d_indptr[Nn + 1];
__device__ int   d_src[ENt];
__device__ float d_cw[ENt];
__device__ int   d_mcnt[OMt], d_mfill[OMt], d_mptr[OMt + 1];
__device__ int   d_min_[NCt], d_mout[NCt], d_sin[NCt];
__device__ float d_mw[NCt], d_sw[NCt];
__device__ float d_g1[(size_t)(Nn + PADR) * C1t];
__device__ float d_g2[(size_t)(Nn + PADR) * C2t], d_h2[(size_t)(Nn + PADR) * C2t];
// bf16 split activations/weights for mma.sync GEMMs (pad rows stay zero)
__device__ __align__(16) __nv_bfloat16 d_h0h[(size_t)(Nn + PADR) * OMt];
__device__ __align__(16) __nv_bfloat16 d_h0l[(size_t)(Nn + PADR) * OMt];
__device__ __align__(16) __nv_bfloat16 d_h1h[(size_t)(Nn + PADR) * C1t];
__device__ __align__(16) __nv_bfloat16 d_h1l[(size_t)(Nn + PADR) * C1t];
__device__ __align__(16) __nv_bfloat16 d_W1th[C1t * OMt], d_W1tl[C1t * OMt]; // [N][K]
__device__ __align__(16) __nv_bfloat16 d_W2th[C2t * C1t], d_W2tl[C2t * C1t]; // [N][K]
__device__ float d_sum0[OMt], d_sq0[OMt], d_sum1[C1t], d_sq1[C1t], d_sum2[C2t], d_sq2[C2t];
__device__ float d_W1f[OMt * C1t], d_c1[C1t];
__device__ float d_W2f[C1t * C2t], d_c2[C2t];
__device__ float d_Wlf[C2t * 2],  d_c3[2];

__device__ __forceinline__ void bf16split(float v, __nv_bfloat16& h, __nv_bfloat16& l) {
    h = __float2bfloat16(v);
    l = __float2bfloat16(v - __bfloat162float(h));
}

// ---------------- mma.sync helpers (sm_80+, valid on sm_100 base) ----------------
__device__ __forceinline__ void ldsm4(uint32_t* r, uint32_t addr) {
    asm volatile("ldmatrix.sync.aligned.m8n8.x4.shared.b16 {%0,%1,%2,%3}, [%4];"
                 : "=r"(r[0]), "=r"(r[1]), "=r"(r[2]), "=r"(r[3]) : "r"(addr));
}
__device__ __forceinline__ void mma16816(float* d, const uint32_t* a, const uint32_t* b) {
    asm volatile(
        "mma.sync.aligned.m16n8k16.row.col.f32.bf16.bf16.f32 "
        "{%0,%1,%2,%3}, {%4,%5,%6,%7}, {%8,%9}, {%0,%1,%2,%3};"
        : "+f"(d[0]), "+f"(d[1]), "+f"(d[2]), "+f"(d[3])
        : "r"(a[0]), "r"(a[1]), "r"(a[2]), "r"(a[3]), "r"(b[0]), "r"(b[1]));
}

// ---------------- 1: dtype sniff (block 0) + zero all counters/accumulators ----------------
__global__ void k_detect(const unsigned* ei, const unsigned* sm) {
    int t = threadIdx.x, b = blockIdx.x;
    if (b == 0) {
        __shared__ int f0, f1;
        if (t == 0) { f0 = 0; f1 = 0; }
        __syncthreads();
        if (t < 128) {
            if (ei[2 * t + 1]) atomicOr(&f0, 1);
            if (sm[2 * t + 1]) atomicOr(&f1, 1);
        }
        __syncthreads();
        if (t == 0) { g_ei64 = (f0 == 0); g_sm64 = (f1 == 0); }
    }
    int i = b * 256 + t;
    if (i < Nn)  { d_deg[i] = 0.f; d_ecnt[i] = 0; d_fillc[i] = 0; }
    if (i < OMt) { d_mcnt[i] = 0; d_mfill[i] = 0; d_sum0[i] = 0.f; d_sq0[i] = 0.f; }
    if (i < C1t) { d_sum1[i] = 0.f; d_sq1[i] = 0.f; }
    if (i < C2t) { d_sum2[i] = 0.f; d_sq2[i] = 0.f; }
}

// ---------------- 2: decode sparse mask + count per out column ----------------
__global__ void k_maskcount(const void* smv, const float* __restrict__ smw) {
    int j = blockIdx.x * blockDim.x + threadIdx.x;
    if (j >= NCt) return;
    int a, b;
    if (g_sm64) {
        const long long* p = (const long long*)smv;
        a = (int)p[2 * j]; b = (int)p[2 * j + 1];
    } else {
        const int* p = (const int*)smv;
        a = p[2 * j]; b = p[2 * j + 1];
    }
    d_min_[j] = a; d_mout[j] = b; d_mw[j] = smw[j];
    atomicAdd(&d_mcnt[b], 1);
}

// ---------------- 3: single block: scan 512 mask counts + CSC fill ----------------
__global__ void __launch_bounds__(512) k_mask_scanfill() {
    __shared__ int wsum[16];
    int t = threadIdx.x;
    int lane = t & 31, warp = t >> 5;
    int v = d_mcnt[t];
    int s = v;
#pragma unroll
    for (int off = 1; off < 32; off <<= 1) {
        int u = __shfl_up_sync(~0u, s, off);
        if (lane >= off) s += u;
    }
    if (lane == 31) wsum[warp] = s;
    __syncthreads();
    if (warp == 0 && lane < 16) {
        int w = wsum[lane];
#pragma unroll
        for (int off = 1; off < 16; off <<= 1) {
            int u = __shfl_up_sync(0xffffu, w, off);
            if (lane >= off) w += u;
        }
        wsum[lane] = w;
    }
    __syncthreads();
    int incl = s + (warp ? wsum[warp - 1] : 0);
    d_mptr[t] = incl - v;
    if (t == 511) d_mptr[OMt] = incl;
    __syncthreads();
    for (int j = t; j < NCt; j += 512) {
        int b = d_mout[j];
        int p = d_mptr[b] + atomicAdd(&d_mfill[b], 1);
        d_sin[p] = d_min_[j];
        d_sw[p] = d_mw[j];
    }
}

// ---------------- 4 (PROFILED): sparse masked linear + ReLU -> bf16 split only ----------------
#define NPB 4
__global__ void __launch_bounds__(512) k_stageA(const float* __restrict__ x,
                                                const float* __restrict__ smb) {
    __shared__ float4 xs4[INFt];
    int node0 = blockIdx.x * NPB;
    int t = threadIdx.x;
    const float* x0 = x + (size_t)node0 * INFt;
#pragma unroll
    for (int i = 0; i < INFt / 512; i++) {
        int f = t + i * 512;
        float4 v;
        v.x = __ldg(&x0[f]);
        v.y = __ldg(&x0[f + INFt]);
        v.z = __ldg(&x0[f + 2 * INFt]);
        v.w = __ldg(&x0[f + 3 * INFt]);
        xs4[f] = v;
    }
    __syncthreads();
    int o = t;
    float a0 = 0.f, a1 = 0.f, a2 = 0.f, a3 = 0.f;
    int p0 = d_mptr[o], p1 = d_mptr[o + 1];
    for (int p = p0; p < p1; p++) {
        int idx = d_sin[p];
        float w = d_sw[p];
        float4 v = xs4[idx];
        a0 += v.x * w;
        a1 += v.y * w;
        a2 += v.z * w;
        a3 += v.w * w;
    }
    float b = smb[o];
    float vv[4] = {fmaxf(a0 + b, 0.f), fmaxf(a1 + b, 0.f),
                   fmaxf(a2 + b, 0.f), fmaxf(a3 + b, 0.f)};
#pragma unroll
    for (int i = 0; i < 4; i++) {
        size_t off = (size_t)(node0 + i) * OMt + o;
        __nv_bfloat16 h, l;
        bf16split(vv[i], h, l);
        d_h0h[off] = h;
        d_h0l[off] = l;
    }
}

// ---------------- 5: decode edges + per-col degree/count ----------------
__global__ void k_edges(const void* eiv, const float* __restrict__ ew) {
    int e = blockIdx.x * blockDim.x + threadIdx.x;
    if (e >= ENt) return;
    int r, c;
    if (e < Ee) {
        if (g_ei64) {
            const long long* p = (const long long*)eiv;
            r = (int)p[e]; c = (int)p[Ee + e];
        } else {
            const int* p = (const int*)eiv;
            r = p[e]; c = p[Ee + e];
        }
    } else { r = c = e - Ee; }
    float w = (e < Ee) ? ew[e] : 1.f;
    d_ROW[e] = r; d_COL[e] = c;
    atomicAdd(&d_deg[c], w);
    atomicAdd(&d_ecnt[c], 1);
}

// ---------------- 6: shuffle-scan indptr (20000) + dinv ----------------
__global__ void __launch_bounds__(1024) k_scan_dinv() {
    __shared__ int wsum[32];
    const int CH = 20;
    int t = threadIdx.x;
    int lane = t & 31, warp = t >> 5;
    int base = t * CH;
    int cnts[CH];
    int loc = 0;
#pragma unroll
    for (int i = 0; i < CH; i++) {
        int v = (base + i < Nn) ? __ldg(&d_ecnt[base + i]) : 0;
        cnts[i] = v; loc += v;
    }
    int s = loc;
#pragma unroll
    for (int off = 1; off < 32; off <<= 1) {
        int u = __shfl_up_sync(~0u, s, off);
        if (lane >= off) s += u;
    }
    if (lane == 31) wsum[warp] = s;
    __syncthreads();
    if (warp == 0) {
        int w = wsum[lane];
#pragma unroll
        for (int off = 1; off < 32; off <<= 1) {
            int u = __shfl_up_sync(~0u, w, off);
            if (lane >= off) w += u;
        }
        wsum[lane] = w;
    }
    __syncthreads();
    int run = s - loc + (warp ? wsum[warp - 1] : 0);
#pragma unroll
    for (int i = 0; i < CH; i++) {
        if (base + i < Nn) d_indptr[base + i] = run;
        run += cnts[i];
    }
    if (t == 1023) d_indptr[Nn] = run;
    for (int i = t; i < Nn; i += 1024) {
        float dg = d_deg[i];
        d_dinv[i] = (dg > 0.f) ? rsqrtf(dg) : 0.f;
    }
}

// ---------------- 7: CSR fill with normalized weights ----------------
__global__ void k_fill(const float* __restrict__ ew) {
    int e = blockIdx.x * blockDim.x + threadIdx.x;
    if (e >= ENt) return;
    int c = d_COL[e], r = d_ROW[e];
    int p = d_indptr[c] + atomicAdd(&d_fillc[c], 1);
    float w = (e < Ee) ? ew[e] : 1.f;
    d_src[p] = r;
    d_cw[p] = d_dinv[r] * w * d_dinv[c];
}

// ---------------- column stats from bf16 hi/lo pair ----------------
__global__ void k_stats_bf(const __nv_bfloat16* __restrict__ hh,
                           const __nv_bfloat16* __restrict__ hl,
                           float* __restrict__ sum, float* __restrict__ sq, int F) {
    int t = threadIdx.x;   // blockDim == F
    float s = 0.f, q = 0.f;
    for (int r = blockIdx.x; r < Nn; r += gridDim.x) {
        size_t off = (size_t)r * F + t;
        float v = __bfloat162float(hh[off]) + __bfloat162float(hl[off]);
        s += v; q += v * v;
    }
    atomicAdd(&sum[t], s);
    atomicAdd(&sq[t], q);
}

// ---------------- column stats (fp32, for h2) ----------------
__global__ void k_stats(const float* __restrict__ in, float* __restrict__ sum,
                        float* __restrict__ sq, int F) {
    int t = threadIdx.x;
    float s = 0.f, q = 0.f;
    for (int r = blockIdx.x; r < Nn; r += gridDim.x) {
        float v = in[(size_t)r * F + t];
        s += v; q += v * v;
    }
    atomicAdd(&sum[t], s);
    atomicAdd(&sq[t], q);
}

// ---------------- BN-fold: Wf = a⊙W, transposed bf16 hi/lo, c = d@W (+addb) ----------------
__global__ void __launch_bounds__(256) k_prep(
    const float* __restrict__ W, const float* __restrict__ sum,
    const float* __restrict__ sq, const float* __restrict__ g,
    const float* __restrict__ b, const float* __restrict__ addb,
    float* __restrict__ Wf, __nv_bfloat16* __restrict__ Wth,
    __nv_bfloat16* __restrict__ Wtl, float* __restrict__ cvec, int Kd, int Nd) {
    int t = threadIdx.x;
    if (blockIdx.x + 1 < gridDim.x) {
        int i = blockIdx.x * 256 + t;
        if (i < Kd * Nd) {
            int k = i / Nd, n = i - k * Nd;
            float m = sum[k] * (1.f / Nn);
            float v = fmaxf(sq[k] * (1.f / Nn) - m * m, 0.f);
            float s = g[k] * rsqrtf(v + EPSf);
            float w = s * W[i];
            Wf[i] = w;
            if (Wth) {
                __nv_bfloat16 h, l;
                bf16split(w, h, l);
                Wth[n * Kd + k] = h;
                Wtl[n * Kd + k] = l;
            }
        }
    } else {
        __shared__ float dsh[512];
        for (int k = t; k < Kd; k += 256) {
            float m = sum[k] * (1.f / Nn);
            float v = fmaxf(sq[k] * (1.f / Nn) - m * m, 0.f);
            float s = g[k] * rsqrtf(v + EPSf);
            dsh[k] = b[k] - m * s;
        }
        __syncthreads();
        if (t < Nd) {
            float s = addb ? addb[t] : 0.f;
            for (int k = 0; k < Kd; k++) s += dsh[k] * W[k * Nd + t];
            cvec[t] = s;
        }
    }
}

// ---------------- bf16-split mma.sync GEMM: C[M,N] = A[M,K] @ Bt[N,K]^T ----------------
#define KC  64
#define LDE 72
__global__ void __launch_bounds__(256) k_gemm_mma(
    const __nv_bfloat16* __restrict__ Ah, const __nv_bfloat16* __restrict__ Al,
    const __nv_bfloat16* __restrict__ Bh, const __nv_bfloat16* __restrict__ Bl,
    float* __restrict__ C, int K, int N) {
    extern __shared__ __align__(16) __nv_bfloat16 sm[];
    __nv_bfloat16* sAh = sm;
    __nv_bfloat16* sAl = sm + 128 * LDE;
    __nv_bfloat16* sBh = sm + 2 * 128 * LDE;
    __nv_bfloat16* sBl = sm + 3 * 128 * LDE;
    uint32_t base_sa = (uint32_t)__cvta_generic_to_shared(sAh);
    uint32_t base_sb = (uint32_t)__cvta_generic_to_shared(sBh);
    const uint32_t LOFF = 128 * LDE * 2;

    int t = threadIdx.x;
    int warp = t >> 5, lane = t & 31;
    int wm = warp & 1, wn = warp >> 1;
    int mb = blockIdx.x * 128, nb = blockIdx.y * 128;

    float acc[4][4][4];
#pragma unroll
    for (int i = 0; i < 4; i++)
#pragma unroll
        for (int j = 0; j < 4; j++)
#pragma unroll
            for (int e = 0; e < 4; e++) acc[i][j][e] = 0.f;

    int a_r = lane & 15, a_c8 = lane >> 4;
    int b_r = ((lane >> 4) << 3) + (lane & 7);
    int b_c8 = (lane >> 3) & 1;

    for (int kt = 0; kt < K; kt += KC) {
        for (int i = t; i < 1024; i += 256) {
            int row = i >> 3, u = i & 7;
            size_t goA = (size_t)(mb + row) * K + kt + u * 8;
            size_t goB = (size_t)(nb + row) * K + kt + u * 8;
            int so = row * LDE + u * 8;
            *(uint4*)(sAh + so) = *(const uint4*)(Ah + goA);
            *(uint4*)(sAl + so) = *(const uint4*)(Al + goA);
            *(uint4*)(sBh + so) = *(const uint4*)(Bh + goB);
            *(uint4*)(sBl + so) = *(const uint4*)(Bl + goB);
        }
        __syncthreads();
#pragma unroll
        for (int ks = 0; ks < KC; ks += 16) {
            uint32_t aH[4][4], aL[4][4];
#pragma unroll
            for (int mi = 0; mi < 4; mi++) {
                uint32_t off = (uint32_t)((wm * 64 + mi * 16 + a_r) * LDE +
                                          ks + a_c8 * 8) * 2;
                ldsm4(aH[mi], base_sa + off);
                ldsm4(aL[mi], base_sa + LOFF + off);
            }
            uint32_t bH[4][2], bL[4][2];
#pragma unroll
            for (int np = 0; np < 2; np++) {
                uint32_t off = (uint32_t)((wn * 32 + np * 16 + b_r) * LDE +
                                          ks + b_c8 * 8) * 2;
                uint32_t rh[4], rl[4];
                ldsm4(rh, base_sb + off);
                ldsm4(rl, base_sb + LOFF + off);
                bH[np * 2][0] = rh[0]; bH[np * 2][1] = rh[1];
                bH[np * 2 + 1][0] = rh[2]; bH[np * 2 + 1][1] = rh[3];
                bL[np * 2][0] = rl[0]; bL[np * 2][1] = rl[1];
                bL[np * 2 + 1][0] = rl[2]; bL[np * 2 + 1][1] = rl[3];
            }
#pragma unroll
            for (int mi = 0; mi < 4; mi++)
#pragma unroll
                for (int ni = 0; ni < 4; ni++) {
                    mma16816(acc[mi][ni], aH[mi], bH[ni]);
                    mma16816(acc[mi][ni], aL[mi], bH[ni]);
                    mma16816(acc[mi][ni], aH[mi], bL[ni]);
                }
        }
        __syncthreads();
    }
#pragma unroll
    for (int mi = 0; mi < 4; mi++) {
        int row = mb + wm * 64 + mi * 16 + (lane >> 2);
#pragma unroll
        for (int ni = 0; ni < 4; ni++) {
            int col = nb + wn * 32 + ni * 8 + (lane & 3) * 2;
            *(float2*)(C + (size_t)row * N + col) =
                make_float2(acc[mi][ni][0], acc[mi][ni][1]);
            *(float2*)(C + (size_t)(row + 8) * N + col) =
                make_float2(acc[mi][ni][2], acc[mi][ni][3]);
        }
    }
}

// ---------------- CSR agg: 2 cols/thread; out fp32 optional, bf16 split optional ----------------
__global__ void k_agg(const float* __restrict__ g, const float* __restrict__ cv,
                      const float* __restrict__ bias, float* __restrict__ out,
                      __nv_bfloat16* __restrict__ oh, __nv_bfloat16* __restrict__ ol,
                      int F) {
    int n = blockIdx.x, t = threadIdx.x;   // blockDim == F/2
    int c0 = 2 * t;
    int s0 = d_indptr[n], s1 = d_indptr[n + 1];
    float a0 = 0.f, a1 = 0.f, ws = 0.f;
    for (int e = s0; e < s1; e++) {
        int s = __ldg(&d_src[e]);
        float w = __ldg(&d_cw[e]);
        ws += w;
        float2 gv = *(const float2*)(g + (size_t)s * F + c0);
        a0 += gv.x * w;
        a1 += gv.y * w;
    }
    float v0 = fmaxf(a0 + ws * cv[c0] + bias[c0], 0.f);
    float v1 = fmaxf(a1 + ws * cv[c0 + 1] + bias[c0 + 1], 0.f);
    size_t off = (size_t)n * F + c0;
    if (out) *(float2*)(out + off) = make_float2(v0, v1);
    if (oh) {
        __nv_bfloat16 h0, l0, h1, l1;
        bf16split(v0, h0, l0);
        bf16split(v1, h1, l1);
        __nv_bfloat162 hp, lp;
        hp.x = h0; hp.y = h1;
        lp.x = l0; lp.y = l1;
        *(__nv_bfloat162*)(oh + off) = hp;
        *(__nv_bfloat162*)(ol + off) = lp;
    }
}

// ---------------- final linear: out[n,:2] = h2[n,:] @ Wlf + c3 ----------------
__global__ void k_final(float* __restrict__ out) {
    int w = blockIdx.x * 8 + (threadIdx.x >> 5);
    int lane = threadIdx.x & 31;
    if (w >= Nn) return;
    float4 v = ((const float4*)(d_h2 + (size_t)w * C2t))[lane];
    float4 w0 = ((const float4*)d_Wlf)[lane * 2];
    float4 w1 = ((const float4*)d_Wlf)[lane * 2 + 1];
    float s0 = v.x * w0.x + v.y * w0.z + v.z * w1.x + v.w * w1.z;
    float s1 = v.x * w0.y + v.y * w0.w + v.z * w1.y + v.w * w1.w;
#pragma unroll
    for (int off = 16; off; off >>= 1) {
        s0 += __shfl_down_sync(0xffffffffu, s0, off);
        s1 += __shfl_down_sync(0xffffffffu, s1, off);
    }
    if (lane == 0) {
        out[w * 2 + 0] = s0 + d_c3[0];
        out[w * 2 + 1] = s1 + d_c3[1];
    }
}

// ---------------- host launch ----------------
extern "C" void kernel_launch(void* const* d_in, const int* in_sizes, int n_in,
                              void* d_out, int out_size) {
    const float* x     = (const float*)d_in[0];
    const void*  ei    = d_in[1];
    const float* ew    = (const float*)d_in[2];
    const void*  sm    = d_in[3];
    const float* smw   = (const float*)d_in[4];
    const float* smb   = (const float*)d_in[5];
    const float* bnsg  = (const float*)d_in[6];
    const float* bnsb  = (const float*)d_in[7];
    const float* W1    = (const float*)d_in[8];
    const float* b1    = (const float*)d_in[9];
    const float* bn1g  = (const float*)d_in[10];
    const float* bn1b  = (const float*)d_in[11];
    const float* W2    = (const float*)d_in[12];
    const float* b2    = (const float*)d_in[13];
    const float* bn2g  = (const float*)d_in[14];
    const float* bn2b  = (const float*)d_in[15];
    const float* linW  = (const float*)d_in[16];
    const float* linb  = (const float*)d_in[17];
    float* out = (float*)d_out;

    float *p_g1, *p_g2, *p_h2;
    float *p_W1f, *p_W2f, *p_Wlf, *p_c1, *p_c2, *p_c3;
    float *p_s0, *p_q0, *p_s1, *p_q1, *p_s2, *p_q2;
    __nv_bfloat16 *p_h0h, *p_h0l, *p_h1h, *p_h1l;
    __nv_bfloat16 *p_W1th, *p_W1tl, *p_W2th, *p_W2tl;
    cudaGetSymbolAddress((void**)&p_g1, d_g1);
    cudaGetSymbolAddress((void**)&p_g2, d_g2);
    cudaGetSymbolAddress((void**)&p_h2, d_h2);
    cudaGetSymbolAddress((void**)&p_W1f, d_W1f);
    cudaGetSymbolAddress((void**)&p_W2f, d_W2f);
    cudaGetSymbolAddress((void**)&p_Wlf, d_Wlf);
    cudaGetSymbolAddress((void**)&p_c1, d_c1);
    cudaGetSymbolAddress((void**)&p_c2, d_c2);
    cudaGetSymbolAddress((void**)&p_c3, d_c3);
    cudaGetSymbolAddress((void**)&p_s0, d_sum0);
    cudaGetSymbolAddress((void**)&p_q0, d_sq0);
    cudaGetSymbolAddress((void**)&p_s1, d_sum1);
    cudaGetSymbolAddress((void**)&p_q1, d_sq1);
    cudaGetSymbolAddress((void**)&p_s2, d_sum2);
    cudaGetSymbolAddress((void**)&p_q2, d_sq2);
    cudaGetSymbolAddress((void**)&p_h0h, d_h0h);
    cudaGetSymbolAddress((void**)&p_h0l, d_h0l);
    cudaGetSymbolAddress((void**)&p_h1h, d_h1h);
    cudaGetSymbolAddress((void**)&p_h1l, d_h1l);
    cudaGetSymbolAddress((void**)&p_W1th, d_W1th);
    cudaGetSymbolAddress((void**)&p_W1tl, d_W1tl);
    cudaGetSymbolAddress((void**)&p_W2th, d_W2th);
    cudaGetSymbolAddress((void**)&p_W2tl, d_W2tl);

    const int GSM = 4 * 128 * LDE * 2;   // 73728 bytes
    cudaFuncSetAttribute(k_gemm_mma, cudaFuncAttributeMaxDynamicSharedMemorySize, GSM);

    k_detect<<<(Nn + 255) / 256, 256>>>((const unsigned*)ei, (const unsigned*)sm); // 1
    k_maskcount<<<32, 256>>>(sm, smw);                                 // 2
    k_mask_scanfill<<<1, 512>>>();                                     // 3
    k_stageA<<<Nn / NPB, 512>>>(x, smb);                               // 4 <- ncu capture
    k_edges<<<(ENt + 255) / 256, 256>>>(ei, ew);                       // 5
    k_scan_dinv<<<1, 1024>>>();                                        // 6
    k_fill<<<(ENt + 255) / 256, 256>>>(ew);                            // 7

    k_stats_bf<<<256, 512>>>(p_h0h, p_h0l, p_s0, p_q0, OMt);           // 8
    k_prep<<<(OMt * C1t + 255) / 256 + 1, 256>>>(W1, p_s0, p_q0, bnsg, bnsb,
                                                 nullptr, p_W1f, p_W1th, p_W1tl,
                                                 p_c1, OMt, C1t);
    k_gemm_mma<<<dim3((Nn + 127) / 128, C1t / 128), 256, GSM>>>(
        p_h0h, p_h0l, p_W1th, p_W1tl, p_g1, OMt, C1t);
    k_agg<<<Nn, C1t / 2>>>(p_g1, p_c1, b1, nullptr, p_h1h, p_h1l, C1t);

    k_stats_bf<<<256, 256>>>(p_h1h, p_h1l, p_s1, p_q1, C1t);
    k_prep<<<(C1t * C2t + 255) / 256 + 1, 256>>>(W2, p_s1, p_q1, bn1g, bn1b,
                                                 nullptr, p_W2f, p_W2th, p_W2tl,
                                                 p_c2, C1t, C2t);
    k_gemm_mma<<<dim3((Nn + 127) / 128, C2t / 128), 256, GSM>>>(
        p_h1h, p_h1l, p_W2th, p_W2tl, p_g2, C1t, C2t);
    k_agg<<<Nn, C2t / 2>>>(p_g2, p_c2, b2, p_h2, nullptr, nullptr, C2t);

    k_stats<<<256, 128>>>(p_h2, p_s2, p_q2, C2t);
    k_prep<<<2, 256>>>(linW, p_s2, p_q2, bn2g, bn2b, linb, p_Wlf,
                       nullptr, nullptr, p_c3, C2t, 2);
    k_final<<<(Nn + 7) / 8, 256>>>(out);
}